// round 2
// baseline (speedup 1.0000x reference)
#include <cuda_runtime.h>

#define S_LEN 2048
#define D_DIM 4096
#define H_Q   32
#define H_KV  8
#define HDIM  128
#define BATCH 2

// Scratch (allocation-free rule: __device__ globals)
__device__ float g_Q[BATCH * H_Q * S_LEN * HDIM];   // [B, H, S, HD]
__device__ float g_K[BATCH * H_KV * S_LEN * HDIM];  // [B, KV, S, HD]
__device__ float g_V[BATCH * H_KV * S_LEN * HDIM];  // [B, KV, S, HD]
__device__ float g_A[BATCH * S_LEN * H_Q * HDIM];   // [B, S, H, HD] == [M, H*HD]

// ---------------------------------------------------------------------------
// C[m,n] = sum_k A[m,k] * B[n,k]   (both row-major, K contiguous; NT GEMM)
// 128x128 tile, BK=8, 256 threads, 8x8 per thread.
// mode 0: C row-major [M,N].  mode 1: head-permuted store to [B, HC, S, HD].
// ---------------------------------------------------------------------------
__global__ __launch_bounds__(256, 2)
void sgemm_nt(const float* __restrict__ A, const float* __restrict__ B,
              float* __restrict__ C, int M, int N, int K, int mode, int HC)
{
    __shared__ float As[8][132];
    __shared__ float Bs[8][132];
    const int tid = threadIdx.x;
    const int bm = blockIdx.y * 128;
    const int bn = blockIdx.x * 128;
    const int lr = tid >> 1;          // 0..127
    const int lc = (tid & 1) << 2;    // 0 or 4

    const float* Ag = A + (size_t)(bm + lr) * K + lc;
    const float* Bg = B + (size_t)(bn + lr) * K + lc;

    float4 af = *(const float4*)Ag;
    float4 bf = *(const float4*)Bg;

    float acc[8][8];
#pragma unroll
    for (int i = 0; i < 8; i++)
#pragma unroll
        for (int j = 0; j < 8; j++) acc[i][j] = 0.f;

    const int tx = tid & 15;
    const int ty = tid >> 4;

    int k0 = 0;
    for (;;) {
        As[lc + 0][lr] = af.x; As[lc + 1][lr] = af.y;
        As[lc + 2][lr] = af.z; As[lc + 3][lr] = af.w;
        Bs[lc + 0][lr] = bf.x; Bs[lc + 1][lr] = bf.y;
        Bs[lc + 2][lr] = bf.z; Bs[lc + 3][lr] = bf.w;
        __syncthreads();

        k0 += 8;
        const bool more = (k0 < K);
        if (more) {
            af = *(const float4*)(Ag + k0);
            bf = *(const float4*)(Bg + k0);
        }

#pragma unroll
        for (int kk = 0; kk < 8; kk++) {
            float4 a0 = *(const float4*)&As[kk][ty << 2];
            float4 a1 = *(const float4*)&As[kk][(ty << 2) + 64];
            float4 b0 = *(const float4*)&Bs[kk][tx << 2];
            float4 b1 = *(const float4*)&Bs[kk][(tx << 2) + 64];
            float a[8] = {a0.x, a0.y, a0.z, a0.w, a1.x, a1.y, a1.z, a1.w};
            float b[8] = {b0.x, b0.y, b0.z, b0.w, b1.x, b1.y, b1.z, b1.w};
#pragma unroll
            for (int i = 0; i < 8; i++)
#pragma unroll
                for (int j = 0; j < 8; j++)
                    acc[i][j] = fmaf(a[i], b[j], acc[i][j]);
        }
        if (!more) break;
        __syncthreads();
    }

#pragma unroll
    for (int i = 0; i < 8; i++) {
        const int row = (ty << 2) + (i & 3) + ((i >> 2) << 6);
        const int m = bm + row;
#pragma unroll
        for (int j = 0; j < 8; j++) {
            const int col = (tx << 2) + (j & 3) + ((j >> 2) << 6);
            const int n = bn + col;
            if (mode == 0) {
                C[(size_t)m * N + n] = acc[i][j];
            } else {
                const int b = m >> 11, s = m & (S_LEN - 1);
                const int h = n >> 7, hd = n & (HDIM - 1);
                C[(((size_t)(b * HC + h)) * S_LEN + s) * HDIM + hd] = acc[i][j];
            }
        }
    }
}

// ---------------------------------------------------------------------------
// Interleaved RoPE in-place on [B*nheads, S, HD]; one thread per (even,odd) pair.
// ---------------------------------------------------------------------------
__global__ void rope_kernel(float* __restrict__ t, const float* __restrict__ cosb,
                            const float* __restrict__ sinb, int npairs)
{
    const int i = blockIdx.x * blockDim.x + threadIdx.x;
    if (i >= npairs) return;
    const int p = i & 63;                 // freq index, HD/2 = 64
    const int s = (i >> 6) & (S_LEN - 1);
    const int bh = i >> 17;               // 64 * 2048 = 2^17
    const float c = cosb[(s << 6) + p];
    const float sn = sinb[(s << 6) + p];
    float2* ptr = (float2*)(t + ((size_t)bh * S_LEN + s) * HDIM + (p << 1));
    const float2 v = *ptr;
    float2 o;
    o.x = v.x * c - v.y * sn;
    o.y = v.x * sn + v.y * c;
    *ptr = o;
}

// ---------------------------------------------------------------------------
// Flash attention, fp32, causal, GQA (n_rep = 4).
// One CTA per (q-tile of 64, head, batch). 256 threads.
// Score tile 64x64: thread (ty,tx) owns rows 4*ty..+3, score cols tx+16j.
// O tile 64x128: same rows, cols tx*4..+3 and 64+tx*4..+3.
// ---------------------------------------------------------------------------
#define QPAD 132
#define PPAD 68
#define FLASH_SMEM ((3 * 64 * QPAD + 64 * PPAD) * 4)

__global__ __launch_bounds__(256, 1)
void flash_kernel(const float* __restrict__ Q, const float* __restrict__ K,
                  const float* __restrict__ V, float* __restrict__ O)
{
    extern __shared__ float sm[];
    float* Qs = sm;                  // [64][132]
    float* Ks = Qs + 64 * QPAD;      // [64][132]  (row = kv seq, col = hd, swizzled)
    float* Vs = Ks + 64 * QPAD;      // [64][132]
    float* Ps = Vs + 64 * QPAD;      // [64][68]

    const int tid = threadIdx.x;
    const int tx = tid & 15;
    const int ty = tid >> 4;
    const int q0 = blockIdx.x << 6;
    const int h  = blockIdx.y;
    const int b  = blockIdx.z;
    const int kvh = h >> 2;
    const float scale = 0.08838834764831845f; // 1/sqrt(128)

    const float* Qg = Q + (((size_t)(b * H_Q + h)) * S_LEN + q0) * HDIM;
    const float* Kg = K + ((size_t)(b * H_KV + kvh)) * S_LEN * HDIM;
    const float* Vg = V + ((size_t)(b * H_KV + kvh)) * S_LEN * HDIM;

    // Ks rows are stored column-swizzled by bit 3 of the row index.
    // bit3(row tx+16j) == bit3(tx), so each thread deswizzles with its own sw.
    const int sw = ((tx >> 3) & 1) << 2;

    // Load Q tile, pre-scaled
    for (int v = tid; v < 64 * 32; v += 256) {
        const int r = v >> 5, c4 = (v & 31) << 2;
        float4 f = *(const float4*)(Qg + (size_t)r * HDIM + c4);
        f.x *= scale; f.y *= scale; f.z *= scale; f.w *= scale;
        *(float4*)&Qs[r * QPAD + c4] = f;
    }

    float m_run[4], l_run[4];
    float o_acc[4][8];
#pragma unroll
    for (int i = 0; i < 4; i++) {
        m_run[i] = -1e30f; l_run[i] = 0.f;
#pragma unroll
        for (int j = 0; j < 8; j++) o_acc[i][j] = 0.f;
    }

    const int ntiles = (q0 >> 6) + 1;   // causal: only tiles with j0 <= q0
    for (int t = 0; t < ntiles; t++) {
        const int j0 = t << 6;
        __syncthreads();   // prior iter's Ps/Vs reads done before overwrite

        // Load K (column-swizzled per row) and V tiles
        for (int v = tid; v < 64 * 32; v += 256) {
            const int r = v >> 5, c4 = (v & 31) << 2;
            const int ksw = ((r >> 3) & 1) << 2;
            *(float4*)&Ks[r * QPAD + (c4 ^ ksw)] =
                *(const float4*)(Kg + (size_t)(j0 + r) * HDIM + c4);
            *(float4*)&Vs[r * QPAD + c4] =
                *(const float4*)(Vg + (size_t)(j0 + r) * HDIM + c4);
        }
        __syncthreads();

        // S = (Q*scale) K^T
        float s_acc[4][4];
#pragma unroll
        for (int i = 0; i < 4; i++)
#pragma unroll
            for (int j = 0; j < 4; j++) s_acc[i][j] = 0.f;

#pragma unroll 4
        for (int k4 = 0; k4 < HDIM; k4 += 4) {
            float4 aa[4], bb[4];
#pragma unroll
            for (int i = 0; i < 4; i++)
                aa[i] = *(const float4*)&Qs[((ty << 2) + i) * QPAD + k4];
#pragma unroll
            for (int j = 0; j < 4; j++)
                bb[j] = *(const float4*)&Ks[(tx + (j << 4)) * QPAD + (k4 ^ sw)];
#pragma unroll
            for (int i = 0; i < 4; i++)
#pragma unroll
                for (int j = 0; j < 4; j++) {
                    s_acc[i][j] = fmaf(aa[i].x, bb[j].x, s_acc[i][j]);
                    s_acc[i][j] = fmaf(aa[i].y, bb[j].y, s_acc[i][j]);
                    s_acc[i][j] = fmaf(aa[i].z, bb[j].z, s_acc[i][j]);
                    s_acc[i][j] = fmaf(aa[i].w, bb[j].w, s_acc[i][j]);
                }
        }

        // Causal mask + online softmax
        const bool diag = (j0 == q0);
#pragma unroll
        for (int i = 0; i < 4; i++) {
            const int qi = q0 + (ty << 2) + i;
            float mx = -1e30f;
#pragma unroll
            for (int j = 0; j < 4; j++) {
                if (diag && (j0 + tx + (j << 4)) > qi) s_acc[i][j] = -1e30f;
                mx = fmaxf(mx, s_acc[i][j]);
            }
#pragma unroll
            for (int d = 1; d < 16; d <<= 1)
                mx = fmaxf(mx, __shfl_xor_sync(0xffffffffu, mx, d));
            const float mn = fmaxf(m_run[i], mx);
            const float alpha = __expf(m_run[i] - mn);
            float sum = 0.f;
#pragma unroll
            for (int j = 0; j < 4; j++) {
                const float p = __expf(s_acc[i][j] - mn);
                s_acc[i][j] = p;
                sum += p;
            }
#pragma unroll
            for (int d = 1; d < 16; d <<= 1)
                sum += __shfl_xor_sync(0xffffffffu, sum, d);
            l_run[i] = l_run[i] * alpha + sum;
            m_run[i] = mn;
#pragma unroll
            for (int j = 0; j < 8; j++) o_acc[i][j] *= alpha;
#pragma unroll
            for (int j = 0; j < 4; j++)
                Ps[((ty << 2) + i) * PPAD + tx + (j << 4)] = s_acc[i][j];
        }
        __syncthreads();

        // O += P V
#pragma unroll 2
        for (int k = 0; k < 64; k++) {
            const float4 v0 = *(const float4*)&Vs[k * QPAD + (tx << 2)];
            const float4 v1 = *(const float4*)&Vs[k * QPAD + (tx << 2) + 64];
            float pv[4];
#pragma unroll
            for (int i = 0; i < 4; i++)
                pv[i] = Ps[((ty << 2) + i) * PPAD + k];
#pragma unroll
            for (int i = 0; i < 4; i++) {
                o_acc[i][0] = fmaf(pv[i], v0.x, o_acc[i][0]);
                o_acc[i][1] = fmaf(pv[i], v0.y, o_acc[i][1]);
                o_acc[i][2] = fmaf(pv[i], v0.z, o_acc[i][2]);
                o_acc[i][3] = fmaf(pv[i], v0.w, o_acc[i][3]);
                o_acc[i][4] = fmaf(pv[i], v1.x, o_acc[i][4]);
                o_acc[i][5] = fmaf(pv[i], v1.y, o_acc[i][5]);
                o_acc[i][6] = fmaf(pv[i], v1.z, o_acc[i][6]);
                o_acc[i][7] = fmaf(pv[i], v1.w, o_acc[i][7]);
            }
        }
    }

    // Normalize and store to [B, S, H, HD] (== [M, H*HD] for the O-proj GEMM)
#pragma unroll
    for (int i = 0; i < 4; i++) {
        const float inv = 1.f / l_run[i];
        const int s = q0 + (ty << 2) + i;
        float* dst = O + (((size_t)(b * S_LEN + s)) * H_Q + h) * HDIM;
        float4 w0, w1;
        w0.x = o_acc[i][0] * inv; w0.y = o_acc[i][1] * inv;
        w0.z = o_acc[i][2] * inv; w0.w = o_acc[i][3] * inv;
        w1.x = o_acc[i][4] * inv; w1.y = o_acc[i][5] * inv;
        w1.z = o_acc[i][6] * inv; w1.w = o_acc[i][7] * inv;
        *(float4*)(dst + (tx << 2)) = w0;
        *(float4*)(dst + (tx << 2) + 64) = w1;
    }
}

// ---------------------------------------------------------------------------
extern "C" void kernel_launch(void* const* d_in, const int* in_sizes, int n_in,
                              void* d_out, int out_size)
{
    const float* x    = (const float*)d_in[0];
    const float* wq   = (const float*)d_in[1];
    const float* wk   = (const float*)d_in[2];
    const float* wv   = (const float*)d_in[3];
    const float* wo   = (const float*)d_in[4];
    const float* cosb = (const float*)d_in[5];
    const float* sinb = (const float*)d_in[6];
    // d_in[7] = mask (known causal), d_in[8] = start_pos (0) — unused
    float* out = (float*)d_out;

    float *Q, *K, *V, *A;
    cudaGetSymbolAddress((void**)&Q, g_Q);
    cudaGetSymbolAddress((void**)&K, g_K);
    cudaGetSymbolAddress((void**)&V, g_V);
    cudaGetSymbolAddress((void**)&A, g_A);

    const int M = BATCH * S_LEN;   // 4096

    // QKV projections (head-permuted stores)
    sgemm_nt<<<dim3((H_Q * HDIM) / 128, M / 128), 256>>>(x, wq, Q, M, H_Q * HDIM, D_DIM, 1, H_Q);
    sgemm_nt<<<dim3((H_KV * HDIM) / 128, M / 128), 256>>>(x, wk, K, M, H_KV * HDIM, D_DIM, 1, H_KV);
    sgemm_nt<<<dim3((H_KV * HDIM) / 128, M / 128), 256>>>(x, wv, V, M, H_KV * HDIM, D_DIM, 1, H_KV);

    // RoPE on Q and K
    const int qpairs = BATCH * H_Q * S_LEN * (HDIM / 2);   // 8388608
    const int kpairs = BATCH * H_KV * S_LEN * (HDIM / 2);  // 2097152
    rope_kernel<<<(qpairs + 255) / 256, 256>>>(Q, cosb, sinb, qpairs);
    rope_kernel<<<(kpairs + 255) / 256, 256>>>(K, cosb, sinb, kpairs);

    // Flash attention
    cudaFuncSetAttribute(flash_kernel, cudaFuncAttributeMaxDynamicSharedMemorySize, FLASH_SMEM);
    flash_kernel<<<dim3(S_LEN / 64, H_Q, BATCH), 256, FLASH_SMEM>>>(Q, K, V, A);

    // Output projection
    sgemm_nt<<<dim3(D_DIM / 128, M / 128), 256>>>(A, wo, out, M, D_DIM, D_DIM, 0, 0);
}

// round 3
// speedup vs baseline: 1.3671x; 1.3671x over previous
#include <cuda_runtime.h>
#include <cstdint>

#define S_LEN 2048
#define D_DIM 4096
#define H_Q   32
#define H_KV  8
#define HDIM  128
#define BATCH 2

// Scratch (allocation-free rule: __device__ globals)
__device__ float g_Q[BATCH * H_Q * S_LEN * HDIM];   // [B, H, S, HD]
__device__ float g_K[BATCH * H_KV * S_LEN * HDIM];  // [B, KV, S, HD]
__device__ float g_V[BATCH * H_KV * S_LEN * HDIM];  // [B, KV, S, HD]
__device__ float g_A[BATCH * S_LEN * H_Q * HDIM];   // [B, S, H, HD] == [M, H*HD]

__device__ __forceinline__ uint32_t f2tf32(float f) {
    uint32_t u;
    asm("cvt.rna.tf32.f32 %0, %1;" : "=r"(u) : "f"(f));
    return u;
}

// ---------------------------------------------------------------------------
// TF32 tensor-core NT GEMM: C[m,n] = sum_k A[m,k] * B[n,k]
// CTA tile 128x128, BK=32, 256 threads = 8 warps (2 m x 4 n), warp tile 64x32.
// Each warp: 4x4 grid of mma.m16n8k8 tiles. A/B K-transposed in smem,
// stride 136 -> conflict-free fragment loads (bank = 8c + g).
// mode 0: C row-major [M,N].  mode 1: head-permuted store to [B, HC, S, HD].
// ---------------------------------------------------------------------------
#define GSTRIDE 136

__global__ __launch_bounds__(256)
void tf32gemm_nt(const float* __restrict__ A, const float* __restrict__ B,
                 float* __restrict__ C, int M, int N, int K, int mode, int HC)
{
    __shared__ uint32_t As[32 * GSTRIDE];
    __shared__ uint32_t Bs[32 * GSTRIDE];

    const int tid = threadIdx.x;
    const int bm = blockIdx.y << 7;
    const int bn = blockIdx.x << 7;

    // Global load mapping: thread -> row (tid&127), 16 cols starting at (tid>>7)*16.
    const int lr = tid & 127;
    const int lcol = (tid >> 7) << 4;
    const float* Ag = A + (size_t)(bm + lr) * K + lcol;
    const float* Bg = B + (size_t)(bn + lr) * K + lcol;

    // Smem store bases (K-transposed): element [k][m] at k*GSTRIDE + m
    uint32_t* Asw = &As[(size_t)lcol * GSTRIDE + lr];
    uint32_t* Bsw = &Bs[(size_t)lcol * GSTRIDE + lr];

    float4 pa[4], pb[4];
#pragma unroll
    for (int i = 0; i < 4; i++) {
        pa[i] = *(const float4*)(Ag + (i << 2));
        pb[i] = *(const float4*)(Bg + (i << 2));
    }

    const int wid = tid >> 5, lane = tid & 31;
    const int wm = (wid >> 2) << 6;   // 0 or 64
    const int wn = (wid & 3) << 5;    // 0,32,64,96
    const int g = lane >> 2;          // 0..7
    const int c = lane & 3;           // 0..3

    float acc[4][4][4];
#pragma unroll
    for (int mt = 0; mt < 4; mt++)
#pragma unroll
        for (int nt = 0; nt < 4; nt++)
#pragma unroll
            for (int e = 0; e < 4; e++) acc[mt][nt][e] = 0.f;

    int k0 = 0;
    for (;;) {
        // Store stage to smem (transposed + tf32 convert), conflict-free:
        // fixed (i,e): addr = k*136 + lr, lr distinct mod 32 within warp.
#pragma unroll
        for (int i = 0; i < 4; i++) {
            Asw[(i * 4 + 0) * GSTRIDE] = f2tf32(pa[i].x);
            Asw[(i * 4 + 1) * GSTRIDE] = f2tf32(pa[i].y);
            Asw[(i * 4 + 2) * GSTRIDE] = f2tf32(pa[i].z);
            Asw[(i * 4 + 3) * GSTRIDE] = f2tf32(pa[i].w);
            Bsw[(i * 4 + 0) * GSTRIDE] = f2tf32(pb[i].x);
            Bsw[(i * 4 + 1) * GSTRIDE] = f2tf32(pb[i].y);
            Bsw[(i * 4 + 2) * GSTRIDE] = f2tf32(pb[i].z);
            Bsw[(i * 4 + 3) * GSTRIDE] = f2tf32(pb[i].w);
        }
        __syncthreads();

        k0 += 32;
        const bool more = (k0 < K);
        if (more) {
#pragma unroll
            for (int i = 0; i < 4; i++) {
                pa[i] = *(const float4*)(Ag + k0 + (i << 2));
                pb[i] = *(const float4*)(Bg + k0 + (i << 2));
            }
        }

        // Compute 4 k8-steps
#pragma unroll
        for (int ks = 0; ks < 32; ks += 8) {
            uint32_t af[4][4], bf[4][2];
#pragma unroll
            for (int mt = 0; mt < 4; mt++) {
                const int m0 = wm + (mt << 4) + g;
                af[mt][0] = As[(ks + c) * GSTRIDE + m0];
                af[mt][1] = As[(ks + c) * GSTRIDE + m0 + 8];
                af[mt][2] = As[(ks + c + 4) * GSTRIDE + m0];
                af[mt][3] = As[(ks + c + 4) * GSTRIDE + m0 + 8];
            }
#pragma unroll
            for (int nt = 0; nt < 4; nt++) {
                const int n0 = wn + (nt << 3) + g;
                bf[nt][0] = Bs[(ks + c) * GSTRIDE + n0];
                bf[nt][1] = Bs[(ks + c + 4) * GSTRIDE + n0];
            }
#pragma unroll
            for (int mt = 0; mt < 4; mt++)
#pragma unroll
                for (int nt = 0; nt < 4; nt++) {
                    asm volatile(
                        "mma.sync.aligned.m16n8k8.row.col.f32.tf32.tf32.f32 "
                        "{%0,%1,%2,%3}, {%4,%5,%6,%7}, {%8,%9}, {%0,%1,%2,%3};"
                        : "+f"(acc[mt][nt][0]), "+f"(acc[mt][nt][1]),
                          "+f"(acc[mt][nt][2]), "+f"(acc[mt][nt][3])
                        : "r"(af[mt][0]), "r"(af[mt][1]), "r"(af[mt][2]), "r"(af[mt][3]),
                          "r"(bf[nt][0]), "r"(bf[nt][1]));
                }
        }
        if (!more) break;
        __syncthreads();
    }

    // Epilogue. c0,c1 -> (row, 2c), (row, 2c+1); c2,c3 -> (row+8, same cols).
    const int hcol = bn >> 7;   // whole CTA tile lies in one 128-wide head
#pragma unroll
    for (int mt = 0; mt < 4; mt++) {
#pragma unroll
        for (int nt = 0; nt < 4; nt++) {
            const int row = bm + wm + (mt << 4) + g;
            const int col = bn + wn + (nt << 3) + (c << 1);
            float2 lo = make_float2(acc[mt][nt][0], acc[mt][nt][1]);
            float2 hi = make_float2(acc[mt][nt][2], acc[mt][nt][3]);
            if (mode == 0) {
                *(float2*)&C[(size_t)row * N + col] = lo;
                *(float2*)&C[(size_t)(row + 8) * N + col] = hi;
            } else {
                const int hd = col & (HDIM - 1);
                const int b0 = row >> 11, s0 = row & (S_LEN - 1);
                const int b1 = (row + 8) >> 11, s1 = (row + 8) & (S_LEN - 1);
                *(float2*)&C[(((size_t)(b0 * HC + hcol)) * S_LEN + s0) * HDIM + hd] = lo;
                *(float2*)&C[(((size_t)(b1 * HC + hcol)) * S_LEN + s1) * HDIM + hd] = hi;
            }
        }
    }
}

// ---------------------------------------------------------------------------
// Interleaved RoPE in-place on [B*nheads, S, HD]; one thread per (even,odd) pair.
// ---------------------------------------------------------------------------
__global__ void rope_kernel(float* __restrict__ t, const float* __restrict__ cosb,
                            const float* __restrict__ sinb, int npairs)
{
    const int i = blockIdx.x * blockDim.x + threadIdx.x;
    if (i >= npairs) return;
    const int p = i & 63;                 // freq index, HD/2 = 64
    const int s = (i >> 6) & (S_LEN - 1);
    const int bh = i >> 17;               // 64 * 2048 = 2^17
    const float c = cosb[(s << 6) + p];
    const float sn = sinb[(s << 6) + p];
    float2* ptr = (float2*)(t + ((size_t)bh * S_LEN + s) * HDIM + (p << 1));
    const float2 v = *ptr;
    float2 o;
    o.x = v.x * c - v.y * sn;
    o.y = v.x * sn + v.y * c;
    *ptr = o;
}

// ---------------------------------------------------------------------------
// Flash attention, fp32, causal, GQA (n_rep = 4). Unchanged from R2 (correct).
// ---------------------------------------------------------------------------
#define QPAD 132
#define PPAD 68
#define FLASH_SMEM ((3 * 64 * QPAD + 64 * PPAD) * 4)

__global__ __launch_bounds__(256, 1)
void flash_kernel(const float* __restrict__ Q, const float* __restrict__ K,
                  const float* __restrict__ V, float* __restrict__ O)
{
    extern __shared__ float sm[];
    float* Qs = sm;                  // [64][132]
    float* Ks = Qs + 64 * QPAD;      // [64][132]
    float* Vs = Ks + 64 * QPAD;      // [64][132]
    float* Ps = Vs + 64 * QPAD;      // [64][68]

    const int tid = threadIdx.x;
    const int tx = tid & 15;
    const int ty = tid >> 4;
    const int q0 = blockIdx.x << 6;
    const int h  = blockIdx.y;
    const int b  = blockIdx.z;
    const int kvh = h >> 2;
    const float scale = 0.08838834764831845f; // 1/sqrt(128)

    const float* Qg = Q + (((size_t)(b * H_Q + h)) * S_LEN + q0) * HDIM;
    const float* Kg = K + ((size_t)(b * H_KV + kvh)) * S_LEN * HDIM;
    const float* Vg = V + ((size_t)(b * H_KV + kvh)) * S_LEN * HDIM;

    const int sw = ((tx >> 3) & 1) << 2;

    for (int v = tid; v < 64 * 32; v += 256) {
        const int r = v >> 5, c4 = (v & 31) << 2;
        float4 f = *(const float4*)(Qg + (size_t)r * HDIM + c4);
        f.x *= scale; f.y *= scale; f.z *= scale; f.w *= scale;
        *(float4*)&Qs[r * QPAD + c4] = f;
    }

    float m_run[4], l_run[4];
    float o_acc[4][8];
#pragma unroll
    for (int i = 0; i < 4; i++) {
        m_run[i] = -1e30f; l_run[i] = 0.f;
#pragma unroll
        for (int j = 0; j < 8; j++) o_acc[i][j] = 0.f;
    }

    const int ntiles = (q0 >> 6) + 1;
    for (int t = 0; t < ntiles; t++) {
        const int j0 = t << 6;
        __syncthreads();

        for (int v = tid; v < 64 * 32; v += 256) {
            const int r = v >> 5, c4 = (v & 31) << 2;
            const int ksw = ((r >> 3) & 1) << 2;
            *(float4*)&Ks[r * QPAD + (c4 ^ ksw)] =
                *(const float4*)(Kg + (size_t)(j0 + r) * HDIM + c4);
            *(float4*)&Vs[r * QPAD + c4] =
                *(const float4*)(Vg + (size_t)(j0 + r) * HDIM + c4);
        }
        __syncthreads();

        float s_acc[4][4];
#pragma unroll
        for (int i = 0; i < 4; i++)
#pragma unroll
            for (int j = 0; j < 4; j++) s_acc[i][j] = 0.f;

#pragma unroll 4
        for (int k4 = 0; k4 < HDIM; k4 += 4) {
            float4 aa[4], bb[4];
#pragma unroll
            for (int i = 0; i < 4; i++)
                aa[i] = *(const float4*)&Qs[((ty << 2) + i) * QPAD + k4];
#pragma unroll
            for (int j = 0; j < 4; j++)
                bb[j] = *(const float4*)&Ks[(tx + (j << 4)) * QPAD + (k4 ^ sw)];
#pragma unroll
            for (int i = 0; i < 4; i++)
#pragma unroll
                for (int j = 0; j < 4; j++) {
                    s_acc[i][j] = fmaf(aa[i].x, bb[j].x, s_acc[i][j]);
                    s_acc[i][j] = fmaf(aa[i].y, bb[j].y, s_acc[i][j]);
                    s_acc[i][j] = fmaf(aa[i].z, bb[j].z, s_acc[i][j]);
                    s_acc[i][j] = fmaf(aa[i].w, bb[j].w, s_acc[i][j]);
                }
        }

        const bool diag = (j0 == q0);
#pragma unroll
        for (int i = 0; i < 4; i++) {
            const int qi = q0 + (ty << 2) + i;
            float mx = -1e30f;
#pragma unroll
            for (int j = 0; j < 4; j++) {
                if (diag && (j0 + tx + (j << 4)) > qi) s_acc[i][j] = -1e30f;
                mx = fmaxf(mx, s_acc[i][j]);
            }
#pragma unroll
            for (int d = 1; d < 16; d <<= 1)
                mx = fmaxf(mx, __shfl_xor_sync(0xffffffffu, mx, d));
            const float mn = fmaxf(m_run[i], mx);
            const float alpha = __expf(m_run[i] - mn);
            float sum = 0.f;
#pragma unroll
            for (int j = 0; j < 4; j++) {
                const float p = __expf(s_acc[i][j] - mn);
                s_acc[i][j] = p;
                sum += p;
            }
#pragma unroll
            for (int d = 1; d < 16; d <<= 1)
                sum += __shfl_xor_sync(0xffffffffu, sum, d);
            l_run[i] = l_run[i] * alpha + sum;
            m_run[i] = mn;
#pragma unroll
            for (int j = 0; j < 8; j++) o_acc[i][j] *= alpha;
#pragma unroll
            for (int j = 0; j < 4; j++)
                Ps[((ty << 2) + i) * PPAD + tx + (j << 4)] = s_acc[i][j];
        }
        __syncthreads();

#pragma unroll 2
        for (int k = 0; k < 64; k++) {
            const float4 v0 = *(const float4*)&Vs[k * QPAD + (tx << 2)];
            const float4 v1 = *(const float4*)&Vs[k * QPAD + (tx << 2) + 64];
            float pv[4];
#pragma unroll
            for (int i = 0; i < 4; i++)
                pv[i] = Ps[((ty << 2) + i) * PPAD + k];
#pragma unroll
            for (int i = 0; i < 4; i++) {
                o_acc[i][0] = fmaf(pv[i], v0.x, o_acc[i][0]);
                o_acc[i][1] = fmaf(pv[i], v0.y, o_acc[i][1]);
                o_acc[i][2] = fmaf(pv[i], v0.z, o_acc[i][2]);
                o_acc[i][3] = fmaf(pv[i], v0.w, o_acc[i][3]);
                o_acc[i][4] = fmaf(pv[i], v1.x, o_acc[i][4]);
                o_acc[i][5] = fmaf(pv[i], v1.y, o_acc[i][5]);
                o_acc[i][6] = fmaf(pv[i], v1.z, o_acc[i][6]);
                o_acc[i][7] = fmaf(pv[i], v1.w, o_acc[i][7]);
            }
        }
    }

#pragma unroll
    for (int i = 0; i < 4; i++) {
        const float inv = 1.f / l_run[i];
        const int s = q0 + (ty << 2) + i;
        float* dst = O + (((size_t)(b * S_LEN + s)) * H_Q + h) * HDIM;
        float4 w0, w1;
        w0.x = o_acc[i][0] * inv; w0.y = o_acc[i][1] * inv;
        w0.z = o_acc[i][2] * inv; w0.w = o_acc[i][3] * inv;
        w1.x = o_acc[i][4] * inv; w1.y = o_acc[i][5] * inv;
        w1.z = o_acc[i][6] * inv; w1.w = o_acc[i][7] * inv;
        *(float4*)(dst + (tx << 2)) = w0;
        *(float4*)(dst + (tx << 2) + 64) = w1;
    }
}

// ---------------------------------------------------------------------------
extern "C" void kernel_launch(void* const* d_in, const int* in_sizes, int n_in,
                              void* d_out, int out_size)
{
    const float* x    = (const float*)d_in[0];
    const float* wq   = (const float*)d_in[1];
    const float* wk   = (const float*)d_in[2];
    const float* wv   = (const float*)d_in[3];
    const float* wo   = (const float*)d_in[4];
    const float* cosb = (const float*)d_in[5];
    const float* sinb = (const float*)d_in[6];
    float* out = (float*)d_out;

    float *Q, *K, *V, *A;
    cudaGetSymbolAddress((void**)&Q, g_Q);
    cudaGetSymbolAddress((void**)&K, g_K);
    cudaGetSymbolAddress((void**)&V, g_V);
    cudaGetSymbolAddress((void**)&A, g_A);

    const int M = BATCH * S_LEN;   // 4096

    // QKV projections (tf32 tensor cores, head-permuted stores)
    tf32gemm_nt<<<dim3((H_Q * HDIM) / 128, M / 128), 256>>>(x, wq, Q, M, H_Q * HDIM, D_DIM, 1, H_Q);
    tf32gemm_nt<<<dim3((H_KV * HDIM) / 128, M / 128), 256>>>(x, wk, K, M, H_KV * HDIM, D_DIM, 1, H_KV);
    tf32gemm_nt<<<dim3((H_KV * HDIM) / 128, M / 128), 256>>>(x, wv, V, M, H_KV * HDIM, D_DIM, 1, H_KV);

    // RoPE on Q and K
    const int qpairs = BATCH * H_Q * S_LEN * (HDIM / 2);
    const int kpairs = BATCH * H_KV * S_LEN * (HDIM / 2);
    rope_kernel<<<(qpairs + 255) / 256, 256>>>(Q, cosb, sinb, qpairs);
    rope_kernel<<<(kpairs + 255) / 256, 256>>>(K, cosb, sinb, kpairs);

    // Flash attention (fp32)
    cudaFuncSetAttribute(flash_kernel, cudaFuncAttributeMaxDynamicSharedMemorySize, FLASH_SMEM);
    flash_kernel<<<dim3(S_LEN / 64, H_Q, BATCH), 256, FLASH_SMEM>>>(Q, K, V, A);

    // Output projection (tf32 tensor cores)
    tf32gemm_nt<<<dim3(D_DIM / 128, M / 128), 256>>>(A, wo, out, M, D_DIM, D_DIM, 0, 0);
}

// round 4
// speedup vs baseline: 1.7195x; 1.2578x over previous
#include <cuda_runtime.h>
#include <cuda_bf16.h>
#include <cstdint>

#define S_LEN 2048
#define D_DIM 4096
#define H_Q   32
#define H_KV  8
#define HDIM  128
#define BATCH 2

// Scratch (allocation-free rule: __device__ globals)
__device__ float g_Q[BATCH * H_Q * S_LEN * HDIM];   // [B, H, S, HD]
__device__ float g_K[BATCH * H_KV * S_LEN * HDIM];  // [B, KV, S, HD]
__device__ float g_V[BATCH * H_KV * S_LEN * HDIM];  // [B, KV, S, HD]
__device__ float g_A[BATCH * S_LEN * H_Q * HDIM];   // [B, S, H, HD] == [M, H*HD]

__device__ __forceinline__ uint32_t f2tf32(float f) {
    uint32_t u;
    asm("cvt.rna.tf32.f32 %0, %1;" : "=r"(u) : "f"(f));
    return u;
}

// ---------------------------------------------------------------------------
// TF32 tensor-core NT GEMM (unchanged from R3, passing at ~100 TF/s)
// ---------------------------------------------------------------------------
#define GSTRIDE 136

__global__ __launch_bounds__(256)
void tf32gemm_nt(const float* __restrict__ A, const float* __restrict__ B,
                 float* __restrict__ C, int M, int N, int K, int mode, int HC)
{
    __shared__ uint32_t As[32 * GSTRIDE];
    __shared__ uint32_t Bs[32 * GSTRIDE];

    const int tid = threadIdx.x;
    const int bm = blockIdx.y << 7;
    const int bn = blockIdx.x << 7;

    const int lr = tid & 127;
    const int lcol = (tid >> 7) << 4;
    const float* Ag = A + (size_t)(bm + lr) * K + lcol;
    const float* Bg = B + (size_t)(bn + lr) * K + lcol;

    uint32_t* Asw = &As[(size_t)lcol * GSTRIDE + lr];
    uint32_t* Bsw = &Bs[(size_t)lcol * GSTRIDE + lr];

    float4 pa[4], pb[4];
#pragma unroll
    for (int i = 0; i < 4; i++) {
        pa[i] = *(const float4*)(Ag + (i << 2));
        pb[i] = *(const float4*)(Bg + (i << 2));
    }

    const int wid = tid >> 5, lane = tid & 31;
    const int wm = (wid >> 2) << 6;
    const int wn = (wid & 3) << 5;
    const int g = lane >> 2;
    const int c = lane & 3;

    float acc[4][4][4];
#pragma unroll
    for (int mt = 0; mt < 4; mt++)
#pragma unroll
        for (int nt = 0; nt < 4; nt++)
#pragma unroll
            for (int e = 0; e < 4; e++) acc[mt][nt][e] = 0.f;

    int k0 = 0;
    for (;;) {
#pragma unroll
        for (int i = 0; i < 4; i++) {
            Asw[(i * 4 + 0) * GSTRIDE] = f2tf32(pa[i].x);
            Asw[(i * 4 + 1) * GSTRIDE] = f2tf32(pa[i].y);
            Asw[(i * 4 + 2) * GSTRIDE] = f2tf32(pa[i].z);
            Asw[(i * 4 + 3) * GSTRIDE] = f2tf32(pa[i].w);
            Bsw[(i * 4 + 0) * GSTRIDE] = f2tf32(pb[i].x);
            Bsw[(i * 4 + 1) * GSTRIDE] = f2tf32(pb[i].y);
            Bsw[(i * 4 + 2) * GSTRIDE] = f2tf32(pb[i].z);
            Bsw[(i * 4 + 3) * GSTRIDE] = f2tf32(pb[i].w);
        }
        __syncthreads();

        k0 += 32;
        const bool more = (k0 < K);
        if (more) {
#pragma unroll
            for (int i = 0; i < 4; i++) {
                pa[i] = *(const float4*)(Ag + k0 + (i << 2));
                pb[i] = *(const float4*)(Bg + k0 + (i << 2));
            }
        }

#pragma unroll
        for (int ks = 0; ks < 32; ks += 8) {
            uint32_t af[4][4], bf[4][2];
#pragma unroll
            for (int mt = 0; mt < 4; mt++) {
                const int m0 = wm + (mt << 4) + g;
                af[mt][0] = As[(ks + c) * GSTRIDE + m0];
                af[mt][1] = As[(ks + c) * GSTRIDE + m0 + 8];
                af[mt][2] = As[(ks + c + 4) * GSTRIDE + m0];
                af[mt][3] = As[(ks + c + 4) * GSTRIDE + m0 + 8];
            }
#pragma unroll
            for (int nt = 0; nt < 4; nt++) {
                const int n0 = wn + (nt << 3) + g;
                bf[nt][0] = Bs[(ks + c) * GSTRIDE + n0];
                bf[nt][1] = Bs[(ks + c + 4) * GSTRIDE + n0];
            }
#pragma unroll
            for (int mt = 0; mt < 4; mt++)
#pragma unroll
                for (int nt = 0; nt < 4; nt++) {
                    asm volatile(
                        "mma.sync.aligned.m16n8k8.row.col.f32.tf32.tf32.f32 "
                        "{%0,%1,%2,%3}, {%4,%5,%6,%7}, {%8,%9}, {%0,%1,%2,%3};"
                        : "+f"(acc[mt][nt][0]), "+f"(acc[mt][nt][1]),
                          "+f"(acc[mt][nt][2]), "+f"(acc[mt][nt][3])
                        : "r"(af[mt][0]), "r"(af[mt][1]), "r"(af[mt][2]), "r"(af[mt][3]),
                          "r"(bf[nt][0]), "r"(bf[nt][1]));
                }
        }
        if (!more) break;
        __syncthreads();
    }

    const int hcol = bn >> 7;
#pragma unroll
    for (int mt = 0; mt < 4; mt++) {
#pragma unroll
        for (int nt = 0; nt < 4; nt++) {
            const int row = bm + wm + (mt << 4) + g;
            const int col = bn + wn + (nt << 3) + (c << 1);
            float2 lo = make_float2(acc[mt][nt][0], acc[mt][nt][1]);
            float2 hi = make_float2(acc[mt][nt][2], acc[mt][nt][3]);
            if (mode == 0) {
                *(float2*)&C[(size_t)row * N + col] = lo;
                *(float2*)&C[(size_t)(row + 8) * N + col] = hi;
            } else {
                const int hd = col & (HDIM - 1);
                const int b0 = row >> 11, s0 = row & (S_LEN - 1);
                const int b1 = (row + 8) >> 11, s1 = (row + 8) & (S_LEN - 1);
                *(float2*)&C[(((size_t)(b0 * HC + hcol)) * S_LEN + s0) * HDIM + hd] = lo;
                *(float2*)&C[(((size_t)(b1 * HC + hcol)) * S_LEN + s1) * HDIM + hd] = hi;
            }
        }
    }
}

// ---------------------------------------------------------------------------
// RoPE (unchanged)
// ---------------------------------------------------------------------------
__global__ void rope_kernel(float* __restrict__ t, const float* __restrict__ cosb,
                            const float* __restrict__ sinb, int npairs)
{
    const int i = blockIdx.x * blockDim.x + threadIdx.x;
    if (i >= npairs) return;
    const int p = i & 63;
    const int s = (i >> 6) & (S_LEN - 1);
    const int bh = i >> 17;
    const float c = cosb[(s << 6) + p];
    const float sn = sinb[(s << 6) + p];
    float2* ptr = (float2*)(t + ((size_t)bh * S_LEN + s) * HDIM + (p << 1));
    const float2 v = *ptr;
    float2 o;
    o.x = v.x * c - v.y * sn;
    o.y = v.x * sn + v.y * c;
    *ptr = o;
}

// ---------------------------------------------------------------------------
// Flash attention on tensor cores: split-bf16 (hi+lo), 3 MMAs per product.
// q-tile 128 x kv-tile 64, 8 warps; warp w owns q rows [16w, 16w+16).
// ---------------------------------------------------------------------------
#define FSTR 136   // bf16 row stride (128 + 8 pad)
#define FLASH_SMEM ((2 * 128 * FSTR + 4 * 64 * FSTR) * 2)   // 139264 B

__device__ __forceinline__ void ldsm4(uint32_t* r, const __nv_bfloat16* p) {
    uint32_t a = (uint32_t)__cvta_generic_to_shared(p);
    asm volatile("ldmatrix.sync.aligned.m8n8.x4.shared.b16 {%0,%1,%2,%3}, [%4];"
                 : "=r"(r[0]), "=r"(r[1]), "=r"(r[2]), "=r"(r[3]) : "r"(a));
}
__device__ __forceinline__ void ldsm4t(uint32_t* r, const __nv_bfloat16* p) {
    uint32_t a = (uint32_t)__cvta_generic_to_shared(p);
    asm volatile("ldmatrix.sync.aligned.m8n8.x4.trans.shared.b16 {%0,%1,%2,%3}, [%4];"
                 : "=r"(r[0]), "=r"(r[1]), "=r"(r[2]), "=r"(r[3]) : "r"(a));
}
__device__ __forceinline__ void mma_bf16(float* d, const uint32_t* a,
                                         uint32_t b0, uint32_t b1) {
    asm volatile(
        "mma.sync.aligned.m16n8k16.row.col.f32.bf16.bf16.f32 "
        "{%0,%1,%2,%3}, {%4,%5,%6,%7}, {%8,%9}, {%0,%1,%2,%3};"
        : "+f"(d[0]), "+f"(d[1]), "+f"(d[2]), "+f"(d[3])
        : "r"(a[0]), "r"(a[1]), "r"(a[2]), "r"(a[3]), "r"(b0), "r"(b1));
}
__device__ __forceinline__ void bsplit(float x, __nv_bfloat16& h, __nv_bfloat16& l) {
    h = __float2bfloat16(x);
    l = __float2bfloat16(x - __bfloat162float(h));
}
__device__ __forceinline__ uint32_t packbf(float a, float b) {
    __nv_bfloat162 t = __floats2bfloat162_rn(a, b);
    return *(uint32_t*)&t;
}

__global__ __launch_bounds__(256, 1)
void flash_bf16(const float* __restrict__ Q, const float* __restrict__ K,
                const float* __restrict__ V, float* __restrict__ O)
{
    extern __shared__ __nv_bfloat16 sm[];
    __nv_bfloat16* Qh = sm;
    __nv_bfloat16* Ql = Qh + 128 * FSTR;
    __nv_bfloat16* Kh = Ql + 128 * FSTR;
    __nv_bfloat16* Kl = Kh + 64 * FSTR;
    __nv_bfloat16* Vh = Kl + 64 * FSTR;
    __nv_bfloat16* Vl = Vh + 64 * FSTR;

    const int tid = threadIdx.x;
    const int lane = tid & 31;
    const int w = tid >> 5;
    const int g = lane >> 2;
    const int c = lane & 3;
    const int m0 = w << 4;

    const int q0 = blockIdx.x << 7;
    const int h  = blockIdx.y;
    const int b  = blockIdx.z;
    const int kvh = h >> 2;
    const float scale = 0.08838834764831845f;

    const float* Qg = Q + (((size_t)(b * H_Q + h)) * S_LEN + q0) * HDIM;
    const float* Kg = K + ((size_t)(b * H_KV + kvh)) * S_LEN * HDIM;
    const float* Vg = V + ((size_t)(b * H_KV + kvh)) * S_LEN * HDIM;

    // Load + split Q (scale folded in)
    for (int v = tid; v < 128 * 32; v += 256) {
        const int r = v >> 5, c4 = (v & 31) << 2;
        float4 f = *(const float4*)(Qg + (size_t)r * HDIM + c4);
        f.x *= scale; f.y *= scale; f.z *= scale; f.w *= scale;
        __nv_bfloat16 h0, l0, h1, l1, h2, l2, h3, l3;
        bsplit(f.x, h0, l0); bsplit(f.y, h1, l1);
        bsplit(f.z, h2, l2); bsplit(f.w, h3, l3);
        __nv_bfloat162* qh = (__nv_bfloat162*)&Qh[r * FSTR + c4];
        __nv_bfloat162* ql = (__nv_bfloat162*)&Ql[r * FSTR + c4];
        qh[0] = __nv_bfloat162(h0, h1); qh[1] = __nv_bfloat162(h2, h3);
        ql[0] = __nv_bfloat162(l0, l1); ql[1] = __nv_bfloat162(l2, l3);
    }

    float m_run[2] = {-1e30f, -1e30f};
    float l_run[2] = {0.f, 0.f};
    float o_acc[16][4];
#pragma unroll
    for (int n = 0; n < 16; n++)
#pragma unroll
        for (int e = 0; e < 4; e++) o_acc[n][e] = 0.f;

    // ldmatrix address components
    const int a_row = m0 + (lane & 15);
    const int a_cofs = (lane >> 4) << 3;
    const int b_rofs = (lane & 7) + ((lane >> 4) << 3);
    const int b_cofs = ((lane >> 3) & 1) << 3;
    const int v_rofs = (lane & 7) + (((lane >> 3) & 1) << 3);
    const int v_cofs = (lane >> 4) << 3;

    const int ntiles = (q0 >> 6) + 2;
    for (int t = 0; t < ntiles; t++) {
        const int j0 = t << 6;
        __syncthreads();

        // Load + split K, V tiles
        for (int v = tid; v < 64 * 32; v += 256) {
            const int r = v >> 5, c4 = (v & 31) << 2;
            float4 fk = *(const float4*)(Kg + (size_t)(j0 + r) * HDIM + c4);
            float4 fv = *(const float4*)(Vg + (size_t)(j0 + r) * HDIM + c4);
            __nv_bfloat16 h0, l0, h1, l1, h2, l2, h3, l3;
            bsplit(fk.x, h0, l0); bsplit(fk.y, h1, l1);
            bsplit(fk.z, h2, l2); bsplit(fk.w, h3, l3);
            __nv_bfloat162* kh = (__nv_bfloat162*)&Kh[r * FSTR + c4];
            __nv_bfloat162* kl = (__nv_bfloat162*)&Kl[r * FSTR + c4];
            kh[0] = __nv_bfloat162(h0, h1); kh[1] = __nv_bfloat162(h2, h3);
            kl[0] = __nv_bfloat162(l0, l1); kl[1] = __nv_bfloat162(l2, l3);
            bsplit(fv.x, h0, l0); bsplit(fv.y, h1, l1);
            bsplit(fv.z, h2, l2); bsplit(fv.w, h3, l3);
            __nv_bfloat162* vh = (__nv_bfloat162*)&Vh[r * FSTR + c4];
            __nv_bfloat162* vl = (__nv_bfloat162*)&Vl[r * FSTR + c4];
            vh[0] = __nv_bfloat162(h0, h1); vh[1] = __nv_bfloat162(h2, h3);
            vl[0] = __nv_bfloat162(l0, l1); vl[1] = __nv_bfloat162(l2, l3);
        }
        __syncthreads();

        // ---- S = Q K^T (split-bf16: QhKh + QhKl + QlKh) ----
        float s[8][4];
#pragma unroll
        for (int n = 0; n < 8; n++)
#pragma unroll
            for (int e = 0; e < 4; e++) s[n][e] = 0.f;

#pragma unroll
        for (int ks = 0; ks < 8; ks++) {
            uint32_t qh[4], ql[4];
            ldsm4(qh, &Qh[a_row * FSTR + (ks << 4) + a_cofs]);
            ldsm4(ql, &Ql[a_row * FSTR + (ks << 4) + a_cofs]);
#pragma unroll
            for (int jj = 0; jj < 4; jj++) {
                uint32_t kh[4], kl[4];
                const int br = (jj << 4) + b_rofs;
                const int bc = (ks << 4) + b_cofs;
                ldsm4(kh, &Kh[br * FSTR + bc]);
                ldsm4(kl, &Kl[br * FSTR + bc]);
                mma_bf16(s[2 * jj],     qh, kh[0], kh[1]);
                mma_bf16(s[2 * jj],     qh, kl[0], kl[1]);
                mma_bf16(s[2 * jj],     ql, kh[0], kh[1]);
                mma_bf16(s[2 * jj + 1], qh, kh[2], kh[3]);
                mma_bf16(s[2 * jj + 1], qh, kl[2], kl[3]);
                mma_bf16(s[2 * jj + 1], ql, kh[2], kh[3]);
            }
        }

        // ---- causal mask (only last two tiles can mask) ----
        if (t >= ntiles - 2) {
            const int r0 = q0 + m0 + g, r1 = r0 + 8;
#pragma unroll
            for (int n = 0; n < 8; n++) {
                const int col = j0 + (n << 3) + (c << 1);
                if (col > r0)     s[n][0] = -1e30f;
                if (col + 1 > r0) s[n][1] = -1e30f;
                if (col > r1)     s[n][2] = -1e30f;
                if (col + 1 > r1) s[n][3] = -1e30f;
            }
        }

        // ---- online softmax (rows g and g+8; quad shuffles) ----
        float mx0 = -1e30f, mx1 = -1e30f;
#pragma unroll
        for (int n = 0; n < 8; n++) {
            mx0 = fmaxf(mx0, fmaxf(s[n][0], s[n][1]));
            mx1 = fmaxf(mx1, fmaxf(s[n][2], s[n][3]));
        }
        mx0 = fmaxf(mx0, __shfl_xor_sync(0xffffffffu, mx0, 1));
        mx0 = fmaxf(mx0, __shfl_xor_sync(0xffffffffu, mx0, 2));
        mx1 = fmaxf(mx1, __shfl_xor_sync(0xffffffffu, mx1, 1));
        mx1 = fmaxf(mx1, __shfl_xor_sync(0xffffffffu, mx1, 2));

        const float mn0 = fmaxf(m_run[0], mx0);
        const float mn1 = fmaxf(m_run[1], mx1);
        const float alpha0 = __expf(m_run[0] - mn0);
        const float alpha1 = __expf(m_run[1] - mn1);
        m_run[0] = mn0; m_run[1] = mn1;

        float sum0 = 0.f, sum1 = 0.f;
        uint32_t ph[16], pl[16];   // [2n] = (c0,c1) row g; [2n+1] = (c2,c3) row g+8
#pragma unroll
        for (int n = 0; n < 8; n++) {
            float p0 = __expf(s[n][0] - mn0);
            float p1 = __expf(s[n][1] - mn0);
            float p2 = __expf(s[n][2] - mn1);
            float p3 = __expf(s[n][3] - mn1);
            sum0 += p0 + p1; sum1 += p2 + p3;
            __nv_bfloat16 h0, l0, h1, l1;
            bsplit(p0, h0, l0); bsplit(p1, h1, l1);
            ph[2 * n] = packbf(__bfloat162float(h0), __bfloat162float(h1));
            pl[2 * n] = packbf(__bfloat162float(l0), __bfloat162float(l1));
            bsplit(p2, h0, l0); bsplit(p3, h1, l1);
            ph[2 * n + 1] = packbf(__bfloat162float(h0), __bfloat162float(h1));
            pl[2 * n + 1] = packbf(__bfloat162float(l0), __bfloat162float(l1));
        }
        sum0 += __shfl_xor_sync(0xffffffffu, sum0, 1);
        sum0 += __shfl_xor_sync(0xffffffffu, sum0, 2);
        sum1 += __shfl_xor_sync(0xffffffffu, sum1, 1);
        sum1 += __shfl_xor_sync(0xffffffffu, sum1, 2);
        l_run[0] = l_run[0] * alpha0 + sum0;
        l_run[1] = l_run[1] * alpha1 + sum1;

#pragma unroll
        for (int n = 0; n < 16; n++) {
            o_acc[n][0] *= alpha0; o_acc[n][1] *= alpha0;
            o_acc[n][2] *= alpha1; o_acc[n][3] *= alpha1;
        }

        // ---- O += P V (split: PhVh + PlVh + PhVl) ----
#pragma unroll
        for (int kk = 0; kk < 4; kk++) {
            uint32_t pah[4] = {ph[4 * kk], ph[4 * kk + 1], ph[4 * kk + 2], ph[4 * kk + 3]};
            uint32_t pal[4] = {pl[4 * kk], pl[4 * kk + 1], pl[4 * kk + 2], pl[4 * kk + 3]};
#pragma unroll
            for (int jj = 0; jj < 8; jj++) {
                uint32_t vh[4], vl[4];
                const int vr = (kk << 4) + v_rofs;
                const int vc = (jj << 4) + v_cofs;
                ldsm4t(vh, &Vh[vr * FSTR + vc]);
                ldsm4t(vl, &Vl[vr * FSTR + vc]);
                mma_bf16(o_acc[2 * jj],     pah, vh[0], vh[1]);
                mma_bf16(o_acc[2 * jj],     pal, vh[0], vh[1]);
                mma_bf16(o_acc[2 * jj],     pah, vl[0], vl[1]);
                mma_bf16(o_acc[2 * jj + 1], pah, vh[2], vh[3]);
                mma_bf16(o_acc[2 * jj + 1], pal, vh[2], vh[3]);
                mma_bf16(o_acc[2 * jj + 1], pah, vl[2], vl[3]);
            }
        }
    }

    // ---- epilogue: normalize, store to [B, S, H, HD] ----
    const float inv0 = 1.f / l_run[0];
    const float inv1 = 1.f / l_run[1];
    const int s0 = q0 + m0 + g;
    const int s1 = s0 + 8;
    float* d0 = O + (((size_t)(b * S_LEN + s0)) * H_Q + h) * HDIM;
    float* d1 = O + (((size_t)(b * S_LEN + s1)) * H_Q + h) * HDIM;
#pragma unroll
    for (int n = 0; n < 16; n++) {
        const int col = (n << 3) + (c << 1);
        *(float2*)(d0 + col) = make_float2(o_acc[n][0] * inv0, o_acc[n][1] * inv0);
        *(float2*)(d1 + col) = make_float2(o_acc[n][2] * inv1, o_acc[n][3] * inv1);
    }
}

// ---------------------------------------------------------------------------
extern "C" void kernel_launch(void* const* d_in, const int* in_sizes, int n_in,
                              void* d_out, int out_size)
{
    const float* x    = (const float*)d_in[0];
    const float* wq   = (const float*)d_in[1];
    const float* wk   = (const float*)d_in[2];
    const float* wv   = (const float*)d_in[3];
    const float* wo   = (const float*)d_in[4];
    const float* cosb = (const float*)d_in[5];
    const float* sinb = (const float*)d_in[6];
    float* out = (float*)d_out;

    float *Q, *K, *V, *A;
    cudaGetSymbolAddress((void**)&Q, g_Q);
    cudaGetSymbolAddress((void**)&K, g_K);
    cudaGetSymbolAddress((void**)&V, g_V);
    cudaGetSymbolAddress((void**)&A, g_A);

    const int M = BATCH * S_LEN;   // 4096

    tf32gemm_nt<<<dim3((H_Q * HDIM) / 128, M / 128), 256>>>(x, wq, Q, M, H_Q * HDIM, D_DIM, 1, H_Q);
    tf32gemm_nt<<<dim3((H_KV * HDIM) / 128, M / 128), 256>>>(x, wk, K, M, H_KV * HDIM, D_DIM, 1, H_KV);
    tf32gemm_nt<<<dim3((H_KV * HDIM) / 128, M / 128), 256>>>(x, wv, V, M, H_KV * HDIM, D_DIM, 1, H_KV);

    const int qpairs = BATCH * H_Q * S_LEN * (HDIM / 2);
    const int kpairs = BATCH * H_KV * S_LEN * (HDIM / 2);
    rope_kernel<<<(qpairs + 255) / 256, 256>>>(Q, cosb, sinb, qpairs);
    rope_kernel<<<(kpairs + 255) / 256, 256>>>(K, cosb, sinb, kpairs);

    cudaFuncSetAttribute(flash_bf16, cudaFuncAttributeMaxDynamicSharedMemorySize, FLASH_SMEM);
    flash_bf16<<<dim3(S_LEN / 128, H_Q, BATCH), 256, FLASH_SMEM>>>(Q, K, V, A);

    tf32gemm_nt<<<dim3(D_DIM / 128, M / 128), 256>>>(A, wo, out, M, D_DIM, D_DIM, 0, 0);
}